// round 1
// baseline (speedup 1.0000x reference)
#include <cuda_runtime.h>
#include <math.h>

#define B_  64
#define T_  512
#define D_  1024
#define H_  1024
#define G4  4096   // 4*H

// ---------------- device-global scratch (alloc-free workaround) ----------------
__device__ float g_Wip[D_ * G4];        // permuted Wi   (16 MB)
__device__ float g_Whp[H_ * G4];        // permuted Wh   (16 MB)
__device__ float g_bp[G4];              // permuted bias
__device__ float g_xp[(size_t)B_ * T_ * G4]; // x_proj [B*T, 4H] permuted cols (512 MB)
__device__ float g_h[2][B_ * H_];       // double-buffered hidden state
__device__ float g_c[B_ * H_];          // cell state

typedef unsigned long long ull;

// ---------------- packed f32x2 helpers ----------------
__device__ __forceinline__ ull pack2(float lo, float hi) {
    ull r;
    asm("mov.b64 %0, {%1, %2};" : "=l"(r) : "f"(lo), "f"(hi));
    return r;
}
__device__ __forceinline__ void unpack2(ull v, float& lo, float& hi) {
    asm("mov.b64 {%0, %1}, %2;" : "=f"(lo), "=f"(hi) : "l"(v));
}
__device__ __forceinline__ void fma2(ull& d, ull a, ull b) {
    asm("fma.rn.f32x2 %0, %1, %2, %0;" : "+l"(d) : "l"(a), "l"(b));
}

__device__ __forceinline__ float sigmoidf_(float x) {
    return 1.0f / (1.0f + expf(-x));
}

// ---------------- phase 0a: permute weights (gate-interleave columns) ----------
// new col n' = hc*4 + g  <-  old col g*1024 + hc
__global__ void permute_kernel(const float* __restrict__ Wi,
                               const float* __restrict__ Wh,
                               const float* __restrict__ b) {
    int idx = blockIdx.x * blockDim.x + threadIdx.x;   // 0 .. 4M-1
    int k  = idx >> 12;        // row
    int np = idx & 4095;       // permuted col
    int hc = np >> 2;
    int gg = np & 3;
    int src = (k << 12) + (gg << 10) + hc;
    g_Wip[idx] = Wi[src];
    g_Whp[idx] = Wh[src];
    if (idx < G4) {
        g_bp[idx] = b[((idx & 3) << 10) + (idx >> 2)];
    }
}

// ---------------- phase 0b: init state ----------------
__global__ void init_state(const float* __restrict__ init_c,
                           const float* __restrict__ init_h) {
    int idx = blockIdx.x * blockDim.x + threadIdx.x;   // 0 .. 65535
    g_c[idx]    = init_c[idx];
    g_h[0][idx] = init_h[idx];
}

// ---------------- phase 1: x_proj = X @ Wip + bp ----------------
// M=32768 N=4096 K=1024.  BM=128 BN=64 BK=16, 256 threads, micro 8m x 4n (f32x2 packed over m)
__global__ __launch_bounds__(256)
void gemm_xproj(const float* __restrict__ X) {
    __shared__ float As[16][128];
    __shared__ float Bs[16][64];

    const int tid = threadIdx.x;
    const int m0 = blockIdx.y * 128;
    const int n0 = blockIdx.x * 64;
    const int tx = tid & 15;        // n micro: n_local = tx*4
    const int ty = tid >> 4;        // m micro: rows ty*8 .. ty*8+7

    // A-tile load mapping: 128 rows x 16 k -> 2 float4 / thread
    const int am = tid >> 1;            // 0..127
    const int ak = (tid & 1) * 4;       // 0 or 4 (plus +8 for second)
    const float* Aptr = X + (size_t)(m0 + am) * 1024 + ak;
    // B-tile load mapping: 16 rows x 64 cols -> 1 float4 / thread
    const int brow = tid >> 4;          // 0..15
    const int bcol = (tid & 15) * 4;    // 0..60
    const float* Bptr = g_Wip + (size_t)brow * G4 + n0 + bcol;

    float4 a0 = *(const float4*)(Aptr);
    float4 a1 = *(const float4*)(Aptr + 8);
    float4 bv = *(const float4*)(Bptr);

    ull acc[4][4];
    #pragma unroll
    for (int i = 0; i < 4; ++i)
        #pragma unroll
        for (int j = 0; j < 4; ++j) acc[i][j] = 0ULL;

    for (int kt = 0; kt < 64; ++kt) {
        // store staged tile into smem (A transposed)
        As[ak + 0][am] = a0.x; As[ak + 1][am] = a0.y;
        As[ak + 2][am] = a0.z; As[ak + 3][am] = a0.w;
        As[ak + 8][am] = a1.x; As[ak + 9][am] = a1.y;
        As[ak +10][am] = a1.z; As[ak +11][am] = a1.w;
        *(float4*)&Bs[brow][bcol] = bv;
        __syncthreads();

        if (kt < 63) {
            Aptr += 16;
            Bptr += (size_t)16 * G4;
            a0 = *(const float4*)(Aptr);
            a1 = *(const float4*)(Aptr + 8);
            bv = *(const float4*)(Bptr);
        }

        #pragma unroll
        for (int k = 0; k < 16; ++k) {
            const ulonglong2* ap = (const ulonglong2*)&As[k][ty * 8];
            ulonglong2 A0 = ap[0];          // rows (0,1),(2,3)
            ulonglong2 A1 = ap[1];          // rows (4,5),(6,7)
            float4 b4 = *(const float4*)&Bs[k][tx * 4];
            ull bp0 = pack2(b4.x, b4.x);
            ull bp1 = pack2(b4.y, b4.y);
            ull bp2 = pack2(b4.z, b4.z);
            ull bp3 = pack2(b4.w, b4.w);
            fma2(acc[0][0], A0.x, bp0); fma2(acc[0][1], A0.x, bp1);
            fma2(acc[0][2], A0.x, bp2); fma2(acc[0][3], A0.x, bp3);
            fma2(acc[1][0], A0.y, bp0); fma2(acc[1][1], A0.y, bp1);
            fma2(acc[1][2], A0.y, bp2); fma2(acc[1][3], A0.y, bp3);
            fma2(acc[2][0], A1.x, bp0); fma2(acc[2][1], A1.x, bp1);
            fma2(acc[2][2], A1.x, bp2); fma2(acc[2][3], A1.x, bp3);
            fma2(acc[3][0], A1.y, bp0); fma2(acc[3][1], A1.y, bp1);
            fma2(acc[3][2], A1.y, bp2); fma2(acc[3][3], A1.y, bp3);
        }
        __syncthreads();
    }

    // epilogue: add bias, store
    float4 bias = *(const float4*)(g_bp + n0 + tx * 4);
    #pragma unroll
    for (int mp = 0; mp < 4; ++mp) {
        float lo0, hi0, lo1, hi1, lo2, hi2, lo3, hi3;
        unpack2(acc[mp][0], lo0, hi0);
        unpack2(acc[mp][1], lo1, hi1);
        unpack2(acc[mp][2], lo2, hi2);
        unpack2(acc[mp][3], lo3, hi3);
        int m = m0 + ty * 8 + mp * 2;
        float4 r0 = make_float4(lo0 + bias.x, lo1 + bias.y, lo2 + bias.z, lo3 + bias.w);
        float4 r1 = make_float4(hi0 + bias.x, hi1 + bias.y, hi2 + bias.z, hi3 + bias.w);
        *(float4*)&g_xp[(size_t)m * G4 + n0 + tx * 4]       = r0;
        *(float4*)&g_xp[(size_t)(m + 1) * G4 + n0 + tx * 4] = r1;
    }
}

// ---------------- phase 2: one LSTM timestep ----------------
// z[64, 4096] = xproj_t + h @ Whp, gate math, state update, outputs.
// Grid: 128 CTAs (32 permuted cols = 8 h-cols each), 128 threads, micro 4m x 4n.
__device__ __forceinline__ void cell_update(int b, int t, int hc, int n,
                                            float z0, float z1, float z2, float z3,
                                            const int* __restrict__ lengths,
                                            float* __restrict__ out,
                                            float* __restrict__ hnext) {
    const float4 xp = *(const float4*)&g_xp[((size_t)b * T_ + t) * G4 + n];
    float zi = z0 + xp.x;
    float zf = z1 + xp.y;
    float zg = z2 + xp.z;
    float zo = z3 + xp.w;
    float ig = sigmoidf_(zi);
    float fg = sigmoidf_(zf);
    float gg = tanhf(zg);
    float og = sigmoidf_(zo);
    int sidx = b * H_ + hc;
    float c = fg * g_c[sidx] + ig * gg;
    float h = og * tanhf(c);
    g_c[sidx] = c;
    hnext[sidx] = h;
    out[((size_t)b * T_ + t) * H_ + hc] = h;
    if (t == lengths[b] - 1) {
        out[(size_t)B_ * T_ * H_ + sidx] = c;                 // final_c
        out[(size_t)B_ * T_ * H_ + (size_t)B_ * H_ + sidx] = h; // final_h
    }
}

__global__ __launch_bounds__(128)
void lstm_step(const int* __restrict__ lengths, float* __restrict__ out, int t) {
    __shared__ float hs[16][64];
    __shared__ float ws[16][32];

    const int tid = threadIdx.x;
    const int n0 = blockIdx.x * 32;
    const int tx = tid & 7;     // n micro: n_local = tx*4 (one full gate quad)
    const int ty = tid >> 3;    // 0..15 -> m rows ty*4 .. ty*4+3

    const float* __restrict__ hbuf = g_h[t & 1];
    float* __restrict__ hnext = g_h[(t + 1) & 1];

    // h-tile: 64 b x 16 k -> 2 float4 / thread (transposed store)
    const int hb = tid >> 1;           // 0..63
    const int hk = (tid & 1) * 4;      // 0 or 4 (+8 second)
    const float* hptr = hbuf + hb * H_ + hk;
    // w-tile: 16 k x 32 n -> 1 float4 / thread
    const int wrow = tid >> 3;         // 0..15
    const int wcol = (tid & 7) * 4;    // 0..28
    const float* wptr = g_Whp + (size_t)wrow * G4 + n0 + wcol;

    float4 h0 = *(const float4*)(hptr);
    float4 h1 = *(const float4*)(hptr + 8);
    float4 wv = *(const float4*)(wptr);

    ull acc[2][4];
    #pragma unroll
    for (int i = 0; i < 2; ++i)
        #pragma unroll
        for (int j = 0; j < 4; ++j) acc[i][j] = 0ULL;

    for (int kt = 0; kt < 64; ++kt) {
        hs[hk + 0][hb] = h0.x; hs[hk + 1][hb] = h0.y;
        hs[hk + 2][hb] = h0.z; hs[hk + 3][hb] = h0.w;
        hs[hk + 8][hb] = h1.x; hs[hk + 9][hb] = h1.y;
        hs[hk +10][hb] = h1.z; hs[hk +11][hb] = h1.w;
        *(float4*)&ws[wrow][wcol] = wv;
        __syncthreads();

        if (kt < 63) {
            hptr += 16;
            wptr += (size_t)16 * G4;
            h0 = *(const float4*)(hptr);
            h1 = *(const float4*)(hptr + 8);
            wv = *(const float4*)(wptr);
        }

        #pragma unroll
        for (int k = 0; k < 16; ++k) {
            ulonglong2 ap = *(const ulonglong2*)&hs[k][ty * 4]; // rows (0,1),(2,3)
            float4 b4 = *(const float4*)&ws[k][tx * 4];
            ull bp0 = pack2(b4.x, b4.x);
            ull bp1 = pack2(b4.y, b4.y);
            ull bp2 = pack2(b4.z, b4.z);
            ull bp3 = pack2(b4.w, b4.w);
            fma2(acc[0][0], ap.x, bp0); fma2(acc[0][1], ap.x, bp1);
            fma2(acc[0][2], ap.x, bp2); fma2(acc[0][3], ap.x, bp3);
            fma2(acc[1][0], ap.y, bp0); fma2(acc[1][1], ap.y, bp1);
            fma2(acc[1][2], ap.y, bp2); fma2(acc[1][3], ap.y, bp3);
        }
        __syncthreads();
    }

    // epilogue: each thread owns 4 batch rows x one full gate quad
    const int n = n0 + tx * 4;
    const int hc = n >> 2;
    #pragma unroll
    for (int p = 0; p < 2; ++p) {
        float l0, u0, l1, u1, l2, u2, l3, u3;
        unpack2(acc[p][0], l0, u0);
        unpack2(acc[p][1], l1, u1);
        unpack2(acc[p][2], l2, u2);
        unpack2(acc[p][3], l3, u3);
        int b = ty * 4 + p * 2;
        cell_update(b,     t, hc, n, l0, l1, l2, l3, lengths, out, hnext);
        cell_update(b + 1, t, hc, n, u0, u1, u2, u3, lengths, out, hnext);
    }
}

// ---------------- launch ----------------
extern "C" void kernel_launch(void* const* d_in, const int* in_sizes, int n_in,
                              void* d_out, int out_size) {
    const float* inputs  = (const float*)d_in[0];
    const int*   lengths = (const int*)  d_in[1];
    const float* init_c  = (const float*)d_in[2];
    const float* init_h  = (const float*)d_in[3];
    const float* Wi      = (const float*)d_in[4];
    const float* Wh      = (const float*)d_in[5];
    const float* b       = (const float*)d_in[6];
    float* out = (float*)d_out;

    permute_kernel<<<(D_ * G4) / 256, 256>>>(Wi, Wh, b);
    init_state<<<(B_ * H_) / 256, 256>>>(init_c, init_h);
    gemm_xproj<<<dim3(G4 / 64, (B_ * T_) / 128), 256>>>(inputs);
    for (int t = 0; t < T_; ++t) {
        lstm_step<<<H_ / 8, 128>>>(lengths, out, t);
    }
}

// round 3
// speedup vs baseline: 1.3545x; 1.3545x over previous
#include <cuda_runtime.h>
#include <math.h>

#define B_  64
#define T_  512
#define D_  1024
#define H_  1024
#define G4  4096   // 4*H

#define NCTA   128
#define NTHR   128
#define COLS_PER_CTA 32          // permuted gate columns per CTA (= 8 hidden cells)
#define KCHUNK 64
#define NCHUNK (H_ / KCHUNK)     // 16

// ---------------- device-global scratch ----------------
__device__ float g_Wip[D_ * G4];              // permuted Wi
__device__ float g_Whp[H_ * G4];              // permuted Wh
__device__ float g_bp[G4];                    // permuted bias
__device__ float g_xp[(size_t)B_ * T_ * G4];  // x_proj [b*T+t][4H] permuted cols
__device__ float g_hT[2][H_ * B_];            // hidden state, TRANSPOSED [hc][b], double buffered
__device__ unsigned g_bar;                    // grid barrier counter

typedef unsigned long long ull;

// ---------------- packed f32x2 helpers ----------------
__device__ __forceinline__ ull pack2(float lo, float hi) {
    ull r; asm("mov.b64 %0, {%1, %2};" : "=l"(r) : "f"(lo), "f"(hi)); return r;
}
__device__ __forceinline__ void unpack2(ull v, float& lo, float& hi) {
    asm("mov.b64 {%0, %1}, %2;" : "=f"(lo), "=f"(hi) : "l"(v));
}
__device__ __forceinline__ void fma2(ull& d, ull a, ull b) {
    asm("fma.rn.f32x2 %0, %1, %2, %0;" : "+l"(d) : "l"(a), "l"(b));
}
__device__ __forceinline__ float sigmoidf_(float x) { return 1.0f / (1.0f + expf(-x)); }

// ---------------- phase 0: permute weights (gate-interleave columns) ----------
// new col n' = hc*4 + g  <-  old col g*1024 + hc
__global__ void permute_kernel(const float* __restrict__ Wi,
                               const float* __restrict__ Wh,
                               const float* __restrict__ b) {
    int idx = blockIdx.x * blockDim.x + threadIdx.x;   // 0 .. 4M-1
    int k  = idx >> 12;
    int np = idx & 4095;
    int hc = np >> 2;
    int gg = np & 3;
    int src = (k << 12) + (gg << 10) + hc;
    g_Wip[idx] = Wi[src];
    g_Whp[idx] = Wh[src];
    if (idx < G4) g_bp[idx] = b[((idx & 3) << 10) + (idx >> 2)];
    if (idx == 0) g_bar = 0u;
}

// ---------------- phase 1: x_proj = X @ Wip + bp (unchanged from R1) ----------
__global__ __launch_bounds__(256)
void gemm_xproj(const float* __restrict__ X) {
    __shared__ float As[16][128];
    __shared__ float Bs[16][64];

    const int tid = threadIdx.x;
    const int m0 = blockIdx.y * 128;
    const int n0 = blockIdx.x * 64;
    const int tx = tid & 15;
    const int ty = tid >> 4;

    const int am = tid >> 1;
    const int ak = (tid & 1) * 4;
    const float* Aptr = X + (size_t)(m0 + am) * 1024 + ak;
    const int brow = tid >> 4;
    const int bcol = (tid & 15) * 4;
    const float* Bptr = g_Wip + (size_t)brow * G4 + n0 + bcol;

    float4 a0 = *(const float4*)(Aptr);
    float4 a1 = *(const float4*)(Aptr + 8);
    float4 bv = *(const float4*)(Bptr);

    ull acc[4][4];
    #pragma unroll
    for (int i = 0; i < 4; ++i)
        #pragma unroll
        for (int j = 0; j < 4; ++j) acc[i][j] = 0ULL;

    for (int kt = 0; kt < 64; ++kt) {
        As[ak + 0][am] = a0.x; As[ak + 1][am] = a0.y;
        As[ak + 2][am] = a0.z; As[ak + 3][am] = a0.w;
        As[ak + 8][am] = a1.x; As[ak + 9][am] = a1.y;
        As[ak +10][am] = a1.z; As[ak +11][am] = a1.w;
        *(float4*)&Bs[brow][bcol] = bv;
        __syncthreads();

        if (kt < 63) {
            Aptr += 16;
            Bptr += (size_t)16 * G4;
            a0 = *(const float4*)(Aptr);
            a1 = *(const float4*)(Aptr + 8);
            bv = *(const float4*)(Bptr);
        }

        #pragma unroll
        for (int k = 0; k < 16; ++k) {
            const ulonglong2* ap = (const ulonglong2*)&As[k][ty * 8];
            ulonglong2 A0 = ap[0];
            ulonglong2 A1 = ap[1];
            float4 b4 = *(const float4*)&Bs[k][tx * 4];
            ull bp0 = pack2(b4.x, b4.x);
            ull bp1 = pack2(b4.y, b4.y);
            ull bp2 = pack2(b4.z, b4.z);
            ull bp3 = pack2(b4.w, b4.w);
            fma2(acc[0][0], A0.x, bp0); fma2(acc[0][1], A0.x, bp1);
            fma2(acc[0][2], A0.x, bp2); fma2(acc[0][3], A0.x, bp3);
            fma2(acc[1][0], A0.y, bp0); fma2(acc[1][1], A0.y, bp1);
            fma2(acc[1][2], A0.y, bp2); fma2(acc[1][3], A0.y, bp3);
            fma2(acc[2][0], A1.x, bp0); fma2(acc[2][1], A1.x, bp1);
            fma2(acc[2][2], A1.x, bp2); fma2(acc[2][3], A1.x, bp3);
            fma2(acc[3][0], A1.y, bp0); fma2(acc[3][1], A1.y, bp1);
            fma2(acc[3][2], A1.y, bp2); fma2(acc[3][3], A1.y, bp3);
        }
        __syncthreads();
    }

    float4 bias = *(const float4*)(g_bp + n0 + tx * 4);
    #pragma unroll
    for (int mp = 0; mp < 4; ++mp) {
        float lo0, hi0, lo1, hi1, lo2, hi2, lo3, hi3;
        unpack2(acc[mp][0], lo0, hi0);
        unpack2(acc[mp][1], lo1, hi1);
        unpack2(acc[mp][2], lo2, hi2);
        unpack2(acc[mp][3], lo3, hi3);
        int m = m0 + ty * 8 + mp * 2;
        float4 r0 = make_float4(lo0 + bias.x, lo1 + bias.y, lo2 + bias.z, lo3 + bias.w);
        float4 r1 = make_float4(hi0 + bias.x, hi1 + bias.y, hi2 + bias.z, hi3 + bias.w);
        *(float4*)&g_xp[(size_t)m * G4 + n0 + tx * 4]       = r0;
        *(float4*)&g_xp[(size_t)(m + 1) * G4 + n0 + tx * 4] = r1;
    }
}

// ---------------- phase 2: persistent LSTM recurrence ----------------
// 128 CTAs x 128 threads. CTA owns 32 permuted cols (8 hidden cells).
// Wh slice (1024x32 = 128KB) resident in SMEM for all 512 steps.
// Thread micro-tile: 4 batch x 4 cols (one full i/f/g/o quad), c in registers.
__global__ __launch_bounds__(NTHR, 1)
void lstm_persistent(const float* __restrict__ init_c,
                     const float* __restrict__ init_h,
                     const int*   __restrict__ lengths,
                     float* __restrict__ out) {
    extern __shared__ float smem[];
    float* ws = smem;                      // [1024][32]  Wh slice
    float* hs = smem + H_ * COLS_PER_CTA;  // [2][64][64] h chunk ping-pong

    const int tid = threadIdx.x;
    const int n0  = blockIdx.x * COLS_PER_CTA;
    const int tx  = tid & 7;       // col quad: n = n0 + tx*4
    const int ty  = tid >> 3;      // batch rows 4ty .. 4ty+3
    const int hc  = (n0 >> 2) + tx;
    const int b0  = ty * 4;

    // ---- load Wh slice into SMEM (once) ----
    #pragma unroll 4
    for (int i = 0; i < 64; ++i) {
        int idx = i * NTHR + tid;          // float4 index, 0..8191
        int k  = idx >> 3;
        int c4 = (idx & 7) * 4;
        *(float4*)&ws[k * COLS_PER_CTA + c4] =
            *(const float4*)&g_Whp[(size_t)k * G4 + n0 + c4];
    }

    // ---- init own h slice (transposed) + private c registers ----
    float creg[4];
    float4 h0v;
    {
        float tmp[4];
        #pragma unroll
        for (int j = 0; j < 4; ++j) {
            creg[j] = init_c[(b0 + j) * H_ + hc];
            tmp[j]  = init_h[(b0 + j) * H_ + hc];
        }
        h0v = make_float4(tmp[0], tmp[1], tmp[2], tmp[3]);
        *(float4*)&g_hT[0][hc * B_ + b0] = h0v;
    }
    int rl[4];
    #pragma unroll
    for (int j = 0; j < 4; ++j) rl[j] = lengths[b0 + j];

    const size_t fc_off = (size_t)B_ * T_ * H_;
    const size_t fh_off = fc_off + (size_t)B_ * H_;
    volatile unsigned* vbar = &g_bar;

    for (int t = 0; t < T_; ++t) {
        const float* __restrict__ hbuf = g_hT[t & 1];
        float* __restrict__ hnext = g_hT[(t + 1) & 1];

        // ---- grid barrier: all h writes for step t-1 (or init) visible ----
        __syncthreads();
        if (tid == 0) {
            __threadfence();
            atomicAdd(&g_bar, 1u);
            unsigned target = (unsigned)NCTA * (unsigned)(t + 1);
            while (*vbar < target) { }
            __threadfence();
        }
        __syncthreads();

        // ---- prefetch xp quads for this step (consumed in epilogue) ----
        float4 xpv[4];
        #pragma unroll
        for (int j = 0; j < 4; ++j)
            xpv[j] = *(const float4*)&g_xp[((size_t)(b0 + j) * T_ + t) * G4 + n0 + tx * 4];

        // ---- GEMM: z[64, 32cols] = h @ Wh_slice ----
        ull acc[2][4];
        #pragma unroll
        for (int p = 0; p < 2; ++p)
            #pragma unroll
            for (int j = 0; j < 4; ++j) acc[p][j] = 0ULL;

        // preload chunk 0
        float4 stg[8];
        #pragma unroll
        for (int q = 0; q < 8; ++q)
            stg[q] = __ldcg((const float4*)(hbuf) + q * NTHR + tid);
        #pragma unroll
        for (int q = 0; q < 8; ++q)
            *((float4*)hs + q * NTHR + tid) = stg[q];
        __syncthreads();

        for (int ch = 0; ch < NCHUNK; ++ch) {
            // issue loads for next chunk early
            if (ch < NCHUNK - 1) {
                const float4* src = (const float4*)(hbuf + (ch + 1) * KCHUNK * B_);
                #pragma unroll
                for (int q = 0; q < 8; ++q) stg[q] = __ldcg(src + q * NTHR + tid);
            }
            const float* hcur = hs + (ch & 1) * (KCHUNK * B_);
            const float* wcur = ws + ch * KCHUNK * COLS_PER_CTA;
            #pragma unroll 8
            for (int kk = 0; kk < KCHUNK; ++kk) {
                ulonglong2 ap = *(const ulonglong2*)(hcur + kk * B_ + b0);
                float4 b4 = *(const float4*)(wcur + kk * COLS_PER_CTA + tx * 4);
                ull bp0 = pack2(b4.x, b4.x);
                ull bp1 = pack2(b4.y, b4.y);
                ull bp2 = pack2(b4.z, b4.z);
                ull bp3 = pack2(b4.w, b4.w);
                fma2(acc[0][0], ap.x, bp0); fma2(acc[0][1], ap.x, bp1);
                fma2(acc[0][2], ap.x, bp2); fma2(acc[0][3], ap.x, bp3);
                fma2(acc[1][0], ap.y, bp0); fma2(acc[1][1], ap.y, bp1);
                fma2(acc[1][2], ap.y, bp2); fma2(acc[1][3], ap.y, bp3);
            }
            if (ch < NCHUNK - 1) {
                float4* dst = (float4*)(hs + ((ch + 1) & 1) * (KCHUNK * B_));
                #pragma unroll
                for (int q = 0; q < 8; ++q) dst[q * NTHR + tid] = stg[q];
            }
            __syncthreads();
        }

        // ---- epilogue: gates + state update for 4 (b, hc) cells ----
        float hres[4];
        #pragma unroll
        for (int p = 0; p < 2; ++p) {
            float zi0, zi1, zf0, zf1, zg0, zg1, zo0, zo1;
            unpack2(acc[p][0], zi0, zi1);
            unpack2(acc[p][1], zf0, zf1);
            unpack2(acc[p][2], zg0, zg1);
            unpack2(acc[p][3], zo0, zo1);
            #pragma unroll
            for (int l = 0; l < 2; ++l) {
                int j = p * 2 + l;
                float zi = (l ? zi1 : zi0) + xpv[j].x;
                float zf = (l ? zf1 : zf0) + xpv[j].y;
                float zg = (l ? zg1 : zg0) + xpv[j].z;
                float zo = (l ? zo1 : zo0) + xpv[j].w;
                float ig = sigmoidf_(zi);
                float fg = sigmoidf_(zf);
                float gg = tanhf(zg);
                float og = sigmoidf_(zo);
                float c = fg * creg[j] + ig * gg;
                float h = og * tanhf(c);
                creg[j] = c;
                hres[j] = h;
                out[((size_t)(b0 + j) * T_ + t) * H_ + hc] = h;
                if (t == rl[j] - 1) {
                    out[fc_off + (b0 + j) * H_ + hc] = c;
                    out[fh_off + (b0 + j) * H_ + hc] = h;
                }
            }
        }
        *(float4*)&hnext[hc * B_ + b0] = make_float4(hres[0], hres[1], hres[2], hres[3]);
    }
}

// ---------------- launch ----------------
extern "C" void kernel_launch(void* const* d_in, const int* in_sizes, int n_in,
                              void* d_out, int out_size) {
    const float* inputs  = (const float*)d_in[0];
    const int*   lengths = (const int*)  d_in[1];
    const float* init_c  = (const float*)d_in[2];
    const float* init_h  = (const float*)d_in[3];
    const float* Wi      = (const float*)d_in[4];
    const float* Wh      = (const float*)d_in[5];
    const float* b       = (const float*)d_in[6];
    float* out = (float*)d_out;

    const int smem_bytes = (H_ * COLS_PER_CTA + 2 * KCHUNK * B_) * sizeof(float); // 160KB
    cudaFuncSetAttribute(lstm_persistent,
                         cudaFuncAttributeMaxDynamicSharedMemorySize, smem_bytes);

    permute_kernel<<<(D_ * G4) / 256, 256>>>(Wi, Wh, b);
    gemm_xproj<<<dim3(G4 / 64, (B_ * T_) / 128), 256>>>(inputs);
    lstm_persistent<<<NCTA, NTHR, smem_bytes>>>(init_c, init_h, lengths, out);
}